// round 17
// baseline (speedup 1.0000x reference)
#include <cuda_runtime.h>
#include <cuda_fp16.h>
#include <cstdint>
#include <math.h>

#define N_TOK   8192
#define D_INP   768
#define D_OUT   64
#define NSPLIT  9                   // uneven key-ranges
#define BN      64                  // keys per tile
#define NTILES_ALL 128              // 8192 / 64
#define GRID_A  288                 // persistent attn CTAs (2 items each)

#define ONES_H2 0x3C003C00u         // fp16x2 (1.0, 1.0)

// ---------------- scratch (device globals) --------------------------------
__device__ __align__(16) uint16_t g_wh[3 * D_INP * D_OUT]; // W as fp16
__device__ __align__(16) uint32_t g_qh[N_TOK * 32];        // f16x2 pairs [tok][32]
__device__ __align__(16) uint32_t g_kh[N_TOK * 32];
__device__ __align__(16) uint32_t g_vh[N_TOK * 32];        // V natural [tok][dim]
__device__ __align__(16) uint32_t g_oph[NSPLIT * N_TOK * 32];  // partials fp16x2
__device__ float g_l[NSPLIT * N_TOK];

#define QSCALE 0.1803368801111372f     // (1/8) * log2(e)

// ---------------- helpers --------------------------------------------------
__device__ __forceinline__ float ex2(float x) {
    float y;
    asm("ex2.approx.f32 %0, %1;" : "=f"(y) : "f"(x));
    return y;
}

__device__ __forceinline__ uint32_t cvt_h2(float x, float y) {
    __half2 H = __floats2half2_rn(x, y);
    return *reinterpret_cast<uint32_t*>(&H);
}

__device__ __forceinline__ void mma16816(float* d, const uint32_t* a,
                                         uint32_t b0, uint32_t b1) {
    asm volatile(
        "mma.sync.aligned.m16n8k16.row.col.f32.f16.f16.f32 "
        "{%0,%1,%2,%3}, {%4,%5,%6,%7}, {%8,%9}, {%0,%1,%2,%3};\n"
        : "+f"(d[0]), "+f"(d[1]), "+f"(d[2]), "+f"(d[3])
        : "r"(a[0]), "r"(a[1]), "r"(a[2]), "r"(a[3]), "r"(b0), "r"(b1));
}

__device__ __forceinline__ uint32_t smem_u32(const void* p) {
    uint32_t a;
    asm("{ .reg .u64 t; cvta.to.shared.u64 t, %1; cvt.u32.u64 %0, t; }"
        : "=r"(a) : "l"(p));
    return a;
}

#define LDSM4(r0, r1, r2, r3, a) \
    asm volatile("ldmatrix.sync.aligned.m8n8.x4.shared.b16 {%0,%1,%2,%3}, [%4];" \
                 : "=r"(r0), "=r"(r1), "=r"(r2), "=r"(r3) : "r"(a))
#define LDSM4T(r0, r1, r2, r3, a) \
    asm volatile("ldmatrix.sync.aligned.m8n8.x4.trans.shared.b16 {%0,%1,%2,%3}, [%4];" \
                 : "=r"(r0), "=r"(r1), "=r"(r2), "=r"(r3) : "r"(a))

#define CP_ASYNC16(d, s) \
    asm volatile("cp.async.cg.shared.global [%0], [%1], 16;" \
                 :: "r"(d), "l"(s) : "memory")
#define CP_COMMIT() asm volatile("cp.async.commit_group;" ::: "memory")
#define CP_WAIT1()  asm volatile("cp.async.wait_group 1;" ::: "memory")
#define CP_WAIT0()  asm volatile("cp.async.wait_group 0;" ::: "memory")
#define STS64(a, v0, v1) \
    asm volatile("st.shared.v2.u32 [%0], {%1,%2};" :: "r"(a), "r"(v0), "r"(v1))

// ---------------- W convert kernel (fp32 -> fp16) ---------------------------
__global__ __launch_bounds__(256)
void split_w_kernel(const float* __restrict__ w0,
                    const float* __restrict__ w1,
                    const float* __restrict__ w2) {
    const float* W = (blockIdx.y == 0) ? w0 : (blockIdx.y == 1) ? w1 : w2;
    int i4 = blockIdx.x * 256 + threadIdx.x;
    size_t base = (size_t)blockIdx.y * (D_INP * D_OUT / 4);
    float4 v = ((const float4*)W)[i4];
    ((uint32_t*)g_wh)[(base + i4) * 2]     = cvt_h2(v.x, v.y);
    ((uint32_t*)g_wh)[(base + i4) * 2 + 1] = cvt_h2(v.z, v.w);
}

// ---------------- fused QKV projection (BM=64, reads fp32 X directly) --------
// grid 128, block 192 (6 warps = 2 row-groups x 3 weights, 2 m-frags each).
#define FXB(i)  ((i) * 9216)            // X fp16 double buffer: 64 rows x 144B
#define FWB(i)  (18432 + (i) * 27648)   // W cp.async stages (3 x 9216 each)
#define FSM_TOTAL (18432 + 2 * 27648)   // 73728

extern __shared__ char fsm[];

__device__ __forceinline__ void fproj_copy_w(uint32_t stg, int kc, int tid) {
#pragma unroll
    for (int it = 0; it < 8; it++) {
        int idw = it * 192 + tid;           // 0..1535
        int widx = idw >> 9;
        int rem = idw & 511;
        int row = rem >> 3, cc = rem & 7;
        CP_ASYNC16(stg + widx * 9216 + row * 144 + cc * 16,
                   (const char*)g_wh + (size_t)widx * (D_INP * D_OUT * 2)
                   + (size_t)(kc * 64 + row) * 128 + cc * 16);
    }
}

__global__ __launch_bounds__(192, 2)
void fproj_kernel(const float* __restrict__ x) {
    const int tid = threadIdx.x;
    const int w = tid >> 5, lane = tid & 31;
    const int r = lane >> 2, c = lane & 3;
    const int g = lane >> 3, lr = lane & 7;
    const uint32_t aoff = ((g & 1) * 8 + lr) * 144 + (g >> 1) * 16;
    const int widx = w % 3;          // weight (Q/K/V)
    const int rg = w / 3;            // row group (0/1): rows rg*32 .. +31
    const int row0 = blockIdx.x * 64;
    const uint32_t sb = smem_u32(fsm);

    float o[2][8][4];
#pragma unroll
    for (int mf = 0; mf < 2; mf++)
#pragma unroll
        for (int nb = 0; nb < 8; nb++)
#pragma unroll
            for (int j = 0; j < 4; j++) o[mf][nb][j] = 0.0f;

    float4 xr[6];

    // ---- prologue: X(0) regs -> smem buf 0 ; W(0) cp.async ----
#pragma unroll
    for (int it = 0; it < 6; it++) {
        int i = it * 192 + tid;
        if (i < 1024) {
            int row = i >> 4, c4 = i & 15;
            xr[it] = *(const float4*)&x[(size_t)(row0 + row) * D_INP + c4 * 4];
        }
    }
    fproj_copy_w(sb + FWB(0), 0, tid);
    CP_COMMIT();
#pragma unroll
    for (int it = 0; it < 6; it++) {
        int i = it * 192 + tid;
        if (i < 1024) {
            int row = i >> 4, c4 = i & 15;
            STS64(sb + FXB(0) + row * 144 + c4 * 8,
                  cvt_h2(xr[it].x, xr[it].y), cvt_h2(xr[it].z, xr[it].w));
        }
    }

    for (int kc = 0; kc < 12; kc++) {
        if (kc + 1 < 12) {
#pragma unroll
            for (int it = 0; it < 6; it++) {
                int i = it * 192 + tid;
                if (i < 1024) {
                    int row = i >> 4, c4 = i & 15;
                    xr[it] = *(const float4*)&x[(size_t)(row0 + row) * D_INP
                                                + (kc + 1) * 64 + c4 * 4];
                }
            }
            fproj_copy_w(sb + FWB((kc + 1) & 1), kc + 1, tid);
            CP_COMMIT();
            CP_WAIT1();
        } else {
            CP_WAIT0();
        }
        __syncthreads();

        if (kc + 1 < 12) {
#pragma unroll
            for (int it = 0; it < 6; it++) {
                int i = it * 192 + tid;
                if (i < 1024) {
                    int row = i >> 4, c4 = i & 15;
                    STS64(sb + FXB((kc + 1) & 1) + row * 144 + c4 * 8,
                          cvt_h2(xr[it].x, xr[it].y), cvt_h2(xr[it].z, xr[it].w));
                }
            }
        }

        const uint32_t xb = sb + FXB(kc & 1);
        const uint32_t wb = sb + FWB(kc & 1);
#pragma unroll
        for (int kb = 0; kb < 4; kb++) {
            uint32_t ah[2][4];
#pragma unroll
            for (int mf = 0; mf < 2; mf++)
                LDSM4(ah[mf][0], ah[mf][1], ah[mf][2], ah[mf][3],
                      xb + (rg * 32 + mf * 16) * 144 + kb * 32 + aoff);
#pragma unroll
            for (int nbp = 0; nbp < 4; nbp++) {
                uint32_t h0, h1, h2, h3;
                LDSM4T(h0, h1, h2, h3,
                       wb + widx * 9216 + kb * (16 * 144) + nbp * 32 + aoff);
#pragma unroll
                for (int mf = 0; mf < 2; mf++) {
                    mma16816(o[mf][2 * nbp],     ah[mf], h0, h1);
                    mma16816(o[mf][2 * nbp + 1], ah[mf], h2, h3);
                }
            }
        }
        __syncthreads();
    }

    uint32_t* HI = (widx == 0) ? g_qh : (widx == 1) ? g_kh : g_vh;
    const float sc = (widx == 0) ? QSCALE : 1.0f;
#pragma unroll
    for (int mf = 0; mf < 2; mf++) {
        int ra = row0 + rg * 32 + mf * 16 + r;
        int rb = ra + 8;
#pragma unroll
        for (int nb = 0; nb < 8; nb++) {
            int pi = nb * 4 + c;
            HI[ra * 32 + pi] = cvt_h2(o[mf][nb][0] * sc, o[mf][nb][1] * sc);
            HI[rb * 32 + pi] = cvt_h2(o[mf][nb][2] * sc, o[mf][nb][3] * sc);
        }
    }
}

// ---------------- flash attention (persistent, pure fp16, MMA l-sum) ---------
#define TILE_B 9216                  // 64 rows * 144 B
#define OFF_KHI 0
#define OFF_VHI TILE_B
#define BUF_B   (2 * TILE_B)         // 18432
#define STAGES  3
#define SMEM_TOTAL (STAGES * BUF_B)  // 55296

extern __shared__ char dsm[];

__device__ __forceinline__ void copy_tile_async(uint32_t sbuf, int k0, int tid) {
#pragma unroll
    for (int it = 0; it < 2; it++) {
        int id = it * 256 + tid;          // 0..511
        int row = id >> 3, cc = id & 7;
        uint32_t doff = row * 144 + cc * 16;
        CP_ASYNC16(sbuf + OFF_KHI + doff,
                   (const char*)g_kh + (size_t)(k0 + row) * 128 + cc * 16);
        CP_ASYNC16(sbuf + OFF_VHI + doff,
                   (const char*)g_vh + (size_t)(k0 + row) * 128 + cc * 16);
    }
}

__global__ __launch_bounds__(256, 2)
void attn_kernel() {
    const int tid = threadIdx.x;
    const int w = tid >> 5, lane = tid & 31;
    const int r = lane >> 2, c = lane & 3;
    const int g = lane >> 3, lr = lane & 7;
    const uint32_t boff = ((g >> 1) * 8 + lr) * 144 + (g & 1) * 16;   // non-trans (K)
    const uint32_t toff = ((g & 1) * 8 + lr) * 144 + (g >> 1) * 16;   // trans (V)
    const uint32_t sb = smem_u32(dsm);

    for (int item = 0; item < 2; item++) {
        const int wi = blockIdx.x + item * GRID_A;     // 0..575
        const int qb = wi / NSPLIT;
        const int ri = wi - qb * NSPLIT;
        const int tile0 = (ri * NTILES_ALL) / NSPLIT;
        const int ntile = ((ri + 1) * NTILES_ALL) / NSPLIT - tile0;
        const int q0 = qb * 128;

        // ---- Q fragments ----
        uint32_t qh[4][4];
        {
            int ra = q0 + w * 16 + r;
            int rb = ra + 8;
#pragma unroll
            for (int kb = 0; kb < 4; kb++) {
                int base = kb * 8 + c;
                qh[kb][0] = g_qh[ra * 32 + base];
                qh[kb][1] = g_qh[rb * 32 + base];
                qh[kb][2] = g_qh[ra * 32 + base + 4];
                qh[kb][3] = g_qh[rb * 32 + base + 4];
            }
        }

        float o[8][4];
#pragma unroll
        for (int nb = 0; nb < 8; nb++)
#pragma unroll
            for (int j = 0; j < 4; j++) o[nb][j] = 0.0f;
        float ol[4] = {0.f, 0.f, 0.f, 0.f};   // l row-sums via ones-column MMA

        copy_tile_async(sb, tile0 * BN, tid);
        CP_COMMIT();
        if (ntile > 1)
            copy_tile_async(sb + BUF_B, (tile0 + 1) * BN, tid);
        CP_COMMIT();

        int stage = 0;
        for (int t = 0; t < ntile; t++) {
            CP_WAIT1();
            __syncthreads();
            const uint32_t bu = sb + stage * BUF_B;

            // ---- S = Q Kᵀ : 1-term fp16 ----
            float s[8][4];
#pragma unroll
            for (int nb = 0; nb < 8; nb++)
#pragma unroll
                for (int j = 0; j < 4; j++) s[nb][j] = 0.0f;

#pragma unroll
            for (int kb = 0; kb < 4; kb++) {
#pragma unroll
                for (int nbp = 0; nbp < 4; nbp++) {
                    uint32_t a = bu + OFF_KHI + nbp * (16 * 144) + kb * 32 + boff;
                    uint32_t h0, h1, h2, h3;
                    LDSM4(h0, h1, h2, h3, a);
                    mma16816(s[2 * nbp],     qh[kb], h0, h1);
                    mma16816(s[2 * nbp + 1], qh[kb], h2, h3);
                }
            }

            // ---- p = exp2(s) via MUFU.EX2 ----
#pragma unroll
            for (int nb = 0; nb < 8; nb++) {
                s[nb][0] = ex2(s[nb][0]);
                s[nb][1] = ex2(s[nb][1]);
                s[nb][2] = ex2(s[nb][2]);
                s[nb][3] = ex2(s[nb][3]);
            }

            // ---- O += P V ; l += P·1 (ones-column MMA) ----
#pragma unroll
            for (int kb = 0; kb < 4; kb++) {
                uint32_t ah[4];
                ah[0] = cvt_h2(s[2 * kb][0],     s[2 * kb][1]);
                ah[1] = cvt_h2(s[2 * kb][2],     s[2 * kb][3]);
                ah[2] = cvt_h2(s[2 * kb + 1][0], s[2 * kb + 1][1]);
                ah[3] = cvt_h2(s[2 * kb + 1][2], s[2 * kb + 1][3]);
#pragma unroll
                for (int nbp = 0; nbp < 4; nbp++) {
                    uint32_t a = bu + OFF_VHI + kb * (16 * 144) + nbp * 32 + toff;
                    uint32_t h0, h1, h2, h3;
                    LDSM4T(h0, h1, h2, h3, a);
                    mma16816(o[2 * nbp],     ah, h0, h1);
                    mma16816(o[2 * nbp + 1], ah, h2, h3);
                }
                mma16816(ol, ah, ONES_H2, ONES_H2);
            }

            if (t + 2 < ntile) {
                int ps = stage + 2; if (ps >= STAGES) ps -= STAGES;
                copy_tile_async(sb + ps * BUF_B, (tile0 + t + 2) * BN, tid);
            }
            CP_COMMIT();
            if (++stage == STAGES) stage = 0;
        }

        // ---- epilogue: partials in fp16 (halved traffic) ----
        {
            size_t orow0 = (size_t)ri * N_TOK + q0 + w * 16 + r;
            size_t orow8 = orow0 + 8;
#pragma unroll
            for (int nb = 0; nb < 8; nb++) {
                int pi = nb * 4 + c;
                g_oph[orow0 * 32 + pi] = cvt_h2(o[nb][0], o[nb][1]);
                g_oph[orow8 * 32 + pi] = cvt_h2(o[nb][2], o[nb][3]);
            }
            if (c == 0) {
                g_l[orow0] = ol[0];
                g_l[orow8] = ol[2];
            }
        }

        CP_WAIT0();
        __syncthreads();     // drain before next item reuses smem
    }
}

// ---------------- merge: O = Σo / Σl (fp16 partials) -------------------------
__global__ __launch_bounds__(256)
void merge_kernel(float* __restrict__ out) {
    int idx = blockIdx.x * blockDim.x + threadIdx.x;
    int row = idx >> 4;
    int p2 = (idx & 15) * 2;          // pair-of-half2 index (4 floats)

    float L = 0.0f;
#pragma unroll
    for (int s = 0; s < NSPLIT; s++) L += g_l[s * N_TOK + row];

    float4 acc = make_float4(0.f, 0.f, 0.f, 0.f);
#pragma unroll
    for (int s = 0; s < NSPLIT; s++) {
        uint2 v = *(const uint2*)&g_oph[(size_t)(s * N_TOK + row) * 32 + p2];
        __half2 a = *reinterpret_cast<__half2*>(&v.x);
        __half2 b = *reinterpret_cast<__half2*>(&v.y);
        acc.x += __low2float(a);  acc.y += __high2float(a);
        acc.z += __low2float(b);  acc.w += __high2float(b);
    }
    float inv = 1.0f / L;
    acc.x *= inv; acc.y *= inv; acc.z *= inv; acc.w *= inv;
    *(float4*)&out[(size_t)row * D_OUT + p2 * 2] = acc;
}

// ---------------- launch ------------------------------------------------------
extern "C" void kernel_launch(void* const* d_in, const int* in_sizes, int n_in,
                              void* d_out, int out_size) {
    const float* x  = (const float*)d_in[0];
    const float* Wk = (const float*)d_in[1];   // Q side (reference swap)
    const float* Wq = (const float*)d_in[2];   // K side
    const float* Wv = (const float*)d_in[3];
    float* out = (float*)d_out;

    cudaFuncSetAttribute(fproj_kernel,
                         cudaFuncAttributeMaxDynamicSharedMemorySize, FSM_TOTAL);
    cudaFuncSetAttribute(attn_kernel,
                         cudaFuncAttributeMaxDynamicSharedMemorySize, SMEM_TOTAL);

    split_w_kernel<<<dim3(D_INP * D_OUT / 4 / 256, 3), 256>>>(Wk, Wq, Wv);
    fproj_kernel<<<128, 192, FSM_TOTAL>>>(x);
    attn_kernel<<<GRID_A, 256, SMEM_TOTAL>>>();
    merge_kernel<<<(N_TOK * 16) / 256, 256>>>(out);
}